// round 16
// baseline (speedup 1.0000x reference)
#include <cuda_runtime.h>
#include <cuda_fp16.h>

#define TT   256   // timesteps
#define BB   512   // batch
#define NCTA 128   // CTAs (one per SM; 128*4 = 512 exactly)
#define RR   4     // batch rows per CTA

typedef unsigned long long u64;

// fp16 weight layout (per matrix), uint4 index:
//   idx4 = mm*1024 + j*4 + ks*2 + qp    mm in [0,32), j in [0,256), ks,qp in {0,1}
// uint4 components (half2 each), with q0 = 2qp, q1 = 2qp+1, ka = ks*128 + mm*4:
//   c0 = (Wq0[ka],   Wq0[ka+1])   c1 = (Wq1[ka],   Wq1[ka+1])
//   c2 = (Wq0[ka+2], Wq0[ka+3])   c3 = (Wq1[ka+2], Wq1[ka+3])
// Wq row = q*256 + j of the original (1024,256) matrix.
// Padded +4096 half2 (1024 uint4) for prefetch overshoot.
__device__ __half2 g_W1h [131072 + 4096];  // from W_hh1
__device__ __half2 g_W2ah[131072 + 4096];  // from W_ih2
__device__ __half2 g_W2bh[131072 + 4096];  // from W_hh2

__global__ void prep_kernel(const float* __restrict__ Whh1,
                            const float* __restrict__ Wih2,
                            const float* __restrict__ Whh2) {
    int e = blockIdx.x * blockDim.x + threadIdx.x;   // half2 index
    if (e >= 131072) return;
    int c    = e & 3;
    int idx4 = e >> 2;
    int rem  = idx4 & 1023;
    int mm   = idx4 >> 10;
    int j    = rem >> 2;
    int ks   = (rem >> 1) & 1;
    int qp   = rem & 1;
    int q    = 2 * qp + (c & 1);
    int k    = ks * 128 + mm * 4 + (c >> 1) * 2;
    int src  = (q * 256 + j) * 256 + k;
    g_W1h[e]  = __floats2half2_rn(Whh1[src], Whh1[src + 1]);
    g_W2ah[e] = __floats2half2_rn(Wih2[src], Wih2[src + 1]);
    g_W2bh[e] = __floats2half2_rn(Whh2[src], Whh2[src + 1]);
}

// ---- f32x2 packed helpers ----
__device__ __forceinline__ u64 pack2(float lo, float hi) {
    u64 r;
    asm("mov.b64 %0, {%1, %2};" : "=l"(r) : "f"(lo), "f"(hi));
    return r;
}
__device__ __forceinline__ void unpack2(u64 v, float& lo, float& hi) {
    asm("mov.b64 {%0, %1}, %2;" : "=f"(lo), "=f"(hi) : "l"(v));
}
__device__ __forceinline__ u64 ffma2(u64 a, u64 b, u64 c) {
    u64 d;
    asm("fma.rn.f32x2 %0, %1, %2, %3;" : "=l"(d) : "l"(a), "l"(b), "l"(c));
    return d;
}
__device__ __forceinline__ float hsum(u64 v) {
    float lo, hi;
    unpack2(v, lo, hi);
    return lo + hi;
}
__device__ __forceinline__ float sigmf(float x) {
    return __fdividef(1.0f, 1.0f + __expf(-x));
}
__device__ __forceinline__ float tanhf_fast(float x) {
    return __fdividef(2.0f, 1.0f + __expf(-2.0f * x)) - 1.0f;
}
// fp16x2 (k-pair of one gate) -> packed f32x2 u64
__device__ __forceinline__ u64 h2tof(unsigned int h2raw) {
    __half2 h = *reinterpret_cast<const __half2*>(&h2raw);
    float2 f = __half22float2(h);
    return pack2(f.x, f.y);
}

// h layout (one buffer = 1032 floats): h[ks:2][m:64][r:4][par:2] with +4-float skew
// between ks halves (516 % 32 = 4 -> no LDS bank conflict between the two halves).
#define HB 1032
#define HADDRF(k, r) (((k) >> 7) * 516 + (((k) & 127) >> 1) * 8 + ((r) * 2) + ((k) & 1))

// one m-iter: 2 half2 (my 2 gates, one k-pair) + 2 LDS.128 (4 rows) -> 8 ffma2
__device__ __forceinline__ void mv2x4(unsigned int w0raw, unsigned int w1raw,
                                      const float* __restrict__ hb, int m,
                                      u64* __restrict__ a0, u64* __restrict__ a1) {
    u64 wg0 = h2tof(w0raw);
    u64 wg1 = h2tof(w1raw);
    const ulonglong2* hp = reinterpret_cast<const ulonglong2*>(hb + m * 8);
    ulonglong2 Ha = hp[0], Hb = hp[1];
    a0[0] = ffma2(wg0, Ha.x, a0[0]);
    a0[1] = ffma2(wg0, Ha.y, a0[1]);
    a0[2] = ffma2(wg0, Hb.x, a0[2]);
    a0[3] = ffma2(wg0, Hb.y, a0[3]);
    a1[0] = ffma2(wg1, Ha.x, a1[0]);
    a1[1] = ffma2(wg1, Ha.y, a1[1]);
    a1[2] = ffma2(wg1, Hb.x, a1[2]);
    a1[3] = ffma2(wg1, Hb.y, a1[3]);
}

// one matvec pass: 32 mm-blocks (64 m-iters over my k-half), depth-2 rotation
__device__ __forceinline__ void mvpass(const uint4* __restrict__ wp,
                                       const float* __restrict__ hb,
                                       u64* __restrict__ a0, u64* __restrict__ a1) {
    uint4 w = __ldg(wp);
    wp += 1024;
#pragma unroll 4
    for (int mm = 0; mm < 32; mm++) {
        uint4 wn = __ldg(wp);   // overshoots into padding at mm=31
        wp += 1024;
        mv2x4(w.x, w.y, hb, mm * 2,     a0, a1);
        mv2x4(w.z, w.w, hb, mm * 2 + 1, a0, a1);
        w = wn;
    }
}

__global__ void __launch_bounds__(1024) lstm_kernel(
    const float* __restrict__ x_in,   // (512,256,2)
    const float* __restrict__ W_ih1,  // (1024,2)
    const float* __restrict__ b_ih1, const float* __restrict__ b_hh1,
    const float* __restrict__ b_ih2, const float* __restrict__ b_hh2,
    const float* __restrict__ W_lin,  // (2,256)
    const float* __restrict__ b_lin,  // (2,)
    float* __restrict__ out)          // (512,256,2)
{
    // double-buffered h: [buf:2][HB floats]
    __shared__ __align__(16) float sh1f[2 * HB];
    __shared__ __align__(16) float sh2f[2 * HB];
    __shared__ float sh_x[2][RR][2];
    __shared__ float sh_wl[2][256];

    const int tid  = threadIdx.x;
    const int qp   = tid & 1;          // gate pair: 0 -> (i,f), 1 -> (g,o)
    const int ks   = (tid >> 1) & 1;   // k-half
    const int j    = tid >> 2;         // hidden unit (0..255)
    const int b0   = blockIdx.x * RR;
    const int lane = tid & 31;
    const int warp = tid >> 5;
    const int rme  = ks * 2 + qp;      // the one batch row this thread owns
    const int rp   = ks * 2 + (qp ^ 1);// partner's row (lane^1)

    // per-thread fp32 constants for my 2 gates (2qp, 2qp+1) of unit j
    float bias1[2], bias2[2], wx0[2], wx1[2];
#pragma unroll
    for (int g = 0; g < 2; g++) {
        int row = (2 * qp + g) * 256 + j;
        bias1[g] = b_ih1[row] + b_hh1[row];
        bias2[g] = b_ih2[row] + b_hh2[row];
        wx0[g] = W_ih1[row * 2 + 0];
        wx1[g] = W_ih1[row * 2 + 1];
    }
    if (tid < 256) {
        sh_wl[0][tid] = W_lin[tid];
        sh_wl[1][tid] = W_lin[256 + tid];
    }
    for (int i = tid; i < 2 * HB; i += 1024) { sh1f[i] = 0.0f; sh2f[i] = 0.0f; }
    if (tid < RR * 2) {  // stage x for t=0
        int r = tid >> 1, c = tid & 1;
        sh_x[0][r][c] = x_in[((b0 + r) * TT + 0) * 2 + c];
    }

    float c1 = 0.0f, c2 = 0.0f;   // cell state for my single row, per layer

    const float blin0 = b_lin[0], blin1 = b_lin[1];
    const uint4* w1base  = reinterpret_cast<const uint4*>(g_W1h)  + (j * 4 + ks * 2 + qp);
    const uint4* w2abase = reinterpret_cast<const uint4*>(g_W2ah) + (j * 4 + ks * 2 + qp);
    const uint4* w2bbase = reinterpret_cast<const uint4*>(g_W2bh) + (j * 4 + ks * 2 + qp);
    const int hwme = HADDRF(j, rme);   // my h write offset (+ buf*HB)

    __syncthreads();

    for (int t = 0; t < TT; t++) {
        const int bw = t & 1;        // buffer written this step
        const int br = bw ^ 1;       // buffer holding prev-step h

        // stage x for t+1 (buffer (t+1)&1 last read two barriers ago)
        if (tid < RR * 2 && t + 1 < TT) {
            int r = tid >> 1, c = tid & 1;
            sh_x[(t + 1) & 1][r][c] = x_in[((b0 + r) * TT + t + 1) * 2 + c];
        }

        u64 a0[4], a1[4];
#pragma unroll
        for (int r = 0; r < 4; r++) { a0[r] = 0ULL; a1[r] = 0ULL; }

        // ===== layer 1 matvec: h1_prev * Whh1^T (my 2 gates, my k-half) =====
        mvpass(w1base, sh1f + br * HB + ks * 516, a0, a1);

        // reduce k-parity + cross-k-half (lane^2), then gate-pair exchange (lane^1)
        float s0[4], s1[4];
#pragma unroll
        for (int r = 0; r < 4; r++) {
            float u = hsum(a0[r]);
            float v = hsum(a1[r]);
            s0[r] = u + __shfl_xor_sync(0xffffffffu, u, 2);
            s1[r] = v + __shfl_xor_sync(0xffffffffu, v, 2);
        }
        {
            // rows 2ks (tA) and 2ks+1 (tB); me = qp ? tB : tA
            float tA0 = ks ? s0[2] : s0[0];
            float tB0 = ks ? s0[3] : s0[1];
            float tA1 = ks ? s1[2] : s1[0];
            float tB1 = ks ? s1[3] : s1[1];
            float sme0 = qp ? tB0 : tA0;
            float sme1 = qp ? tB1 : tA1;
            float sp0  = qp ? tA0 : tB0;
            float sp1  = qp ? tA1 : tB1;
            // full pre-activations (bias + x-term) for my 2 gates
            float xm0 = sh_x[t & 1][rme][0], xm1 = sh_x[t & 1][rme][1];
            float xp0 = sh_x[t & 1][rp][0],  xp1 = sh_x[t & 1][rp][1];
            float ume0 = sme0 + fmaf(xm1, wx1[0], fmaf(xm0, wx0[0], bias1[0]));
            float ume1 = sme1 + fmaf(xm1, wx1[1], fmaf(xm0, wx0[1], bias1[1]));
            float up0  = sp0  + fmaf(xp1, wx1[0], fmaf(xp0, wx0[0], bias1[0]));
            float up1  = sp1  + fmaf(xp1, wx1[1], fmaf(xp0, wx0[1], bias1[1]));
            float rc0 = __shfl_xor_sync(0xffffffffu, up0, 1);
            float rc1 = __shfl_xor_sync(0xffffffffu, up1, 1);
            float gi = qp ? rc0 : ume0;
            float gf = qp ? rc1 : ume1;
            float gg = qp ? ume0 : rc0;
            float go = qp ? ume1 : rc1;
            c1 = sigmf(gf) * c1 + sigmf(gi) * tanhf_fast(gg);
            sh1f[bw * HB + hwme] = sigmf(go) * tanhf_fast(c1);
        }
        __syncthreads();  // S1: h1_new visible; everyone past matvec1

#pragma unroll
        for (int r = 0; r < 4; r++) { a0[r] = 0ULL; a1[r] = 0ULL; }

        // ===== layer 2: h1_new * Wih2^T + h2_prev * Whh2^T =====
        mvpass(w2abase, sh1f + bw * HB + ks * 516, a0, a1);
        mvpass(w2bbase, sh2f + br * HB + ks * 516, a0, a1);

#pragma unroll
        for (int r = 0; r < 4; r++) {
            float u = hsum(a0[r]);
            float v = hsum(a1[r]);
            s0[r] = u + __shfl_xor_sync(0xffffffffu, u, 2);
            s1[r] = v + __shfl_xor_sync(0xffffffffu, v, 2);
        }
        {
            float tA0 = ks ? s0[2] : s0[0];
            float tB0 = ks ? s0[3] : s0[1];
            float tA1 = ks ? s1[2] : s1[0];
            float tB1 = ks ? s1[3] : s1[1];
            float ume0 = (qp ? tB0 : tA0) + bias2[0];
            float ume1 = (qp ? tB1 : tA1) + bias2[1];
            float up0  = (qp ? tA0 : tB0) + bias2[0];
            float up1  = (qp ? tA1 : tB1) + bias2[1];
            float rc0 = __shfl_xor_sync(0xffffffffu, up0, 1);
            float rc1 = __shfl_xor_sync(0xffffffffu, up1, 1);
            float gi = qp ? rc0 : ume0;
            float gf = qp ? rc1 : ume1;
            float gg = qp ? ume0 : rc0;
            float go = qp ? ume1 : rc1;
            c2 = sigmf(gf) * c2 + sigmf(gi) * tanhf_fast(gg);
            sh2f[bw * HB + hwme] = sigmf(go) * tanhf_fast(c2);
        }
        __syncthreads();  // S2: h2_new visible; everyone past matvec2

        // ===== y = h2 * W_lin^T + b_lin : warp r -> batch row r =====
        if (warp < RR) {
            int r = warp;
            const float* h2n = sh2f + bw * HB;
            float v0 = 0.0f, v1 = 0.0f;
#pragma unroll
            for (int mm = 0; mm < 8; mm++) {
                int k = lane + mm * 32;
                float h = h2n[HADDRF(k, r)];
                v0 = fmaf(sh_wl[0][k], h, v0);
                v1 = fmaf(sh_wl[1][k], h, v1);
            }
#pragma unroll
            for (int off = 16; off; off >>= 1) {
                v0 += __shfl_xor_sync(0xffffffffu, v0, off);
                v1 += __shfl_xor_sync(0xffffffffu, v1, off);
            }
            if (lane == 0) {
                out[((b0 + r) * TT + t) * 2 + 0] = v0 + blin0;
                out[((b0 + r) * TT + t) * 2 + 1] = v1 + blin1;
            }
        }
        // S1 of step t+1 seals buffer rotation for laggards
    }
}

extern "C" void kernel_launch(void* const* d_in, const int* in_sizes, int n_in,
                              void* d_out, int out_size) {
    const float* inputs = (const float*)d_in[0];
    const float* W_ih1  = (const float*)d_in[1];
    const float* W_hh1  = (const float*)d_in[2];
    const float* b_ih1  = (const float*)d_in[3];
    const float* b_hh1  = (const float*)d_in[4];
    const float* W_ih2  = (const float*)d_in[5];
    const float* W_hh2  = (const float*)d_in[6];
    const float* b_ih2  = (const float*)d_in[7];
    const float* b_hh2  = (const float*)d_in[8];
    const float* W_lin  = (const float*)d_in[9];
    const float* b_lin  = (const float*)d_in[10];

    prep_kernel<<<512, 256>>>(W_hh1, W_ih2, W_hh2);
    lstm_kernel<<<NCTA, 1024>>>(inputs, W_ih1, b_ih1, b_hh1, b_ih2, b_hh2,
                                W_lin, b_lin, (float*)d_out);
}

// round 17
// speedup vs baseline: 1.0311x; 1.0311x over previous
#include <cuda_runtime.h>
#include <cuda_fp16.h>

#define TT   256   // timesteps
#define BB   512   // batch
#define NCTA 128   // CTAs (one per SM; 128*4 = 512 exactly)
#define RR   4     // batch rows per CTA

typedef unsigned long long u64;

// fp16 weight layout (per matrix), uint4 index:
//   idx4 = m*512 + j*2 + ks     m in [0,64), j in [0,256), ks in {0,1}
// uint4 = 4 half2: component q (0..3) = ( Wq[k0], Wq[k1] ) as half2,
// with k0 = ks*128 + 2m, k1 = k0+1, Wq row = q*256 + j of the original matrix.
// q: 0=i, 1=f, 2=g, 3=o.  Padded +2048 half2 (512 uint4) for prefetch overshoot.
__device__ __half2 g_W1h [131072 + 2048];  // from W_hh1
__device__ __half2 g_W2ah[131072 + 2048];  // from W_ih2
__device__ __half2 g_W2bh[131072 + 2048];  // from W_hh2

__global__ void prep_kernel(const float* __restrict__ Whh1,
                            const float* __restrict__ Wih2,
                            const float* __restrict__ Whh2) {
    int e = blockIdx.x * blockDim.x + threadIdx.x;   // half2 index
    if (e >= 64 * 512 * 4) return;
    int q    = e & 3;
    int idx4 = e >> 2;
    int ks   = idx4 & 1;
    int j    = (idx4 >> 1) & 255;
    int m    = idx4 >> 9;
    int k0   = ks * 128 + 2 * m;
    int src  = (q * 256 + j) * 256 + k0;
    g_W1h[e]  = __floats2half2_rn(Whh1[src], Whh1[src + 1]);
    g_W2ah[e] = __floats2half2_rn(Wih2[src], Wih2[src + 1]);
    g_W2bh[e] = __floats2half2_rn(Whh2[src], Whh2[src + 1]);
}

// ---- f32x2 packed helpers ----
__device__ __forceinline__ u64 pack2(float lo, float hi) {
    u64 r;
    asm("mov.b64 %0, {%1, %2};" : "=l"(r) : "f"(lo), "f"(hi));
    return r;
}
__device__ __forceinline__ void unpack2(u64 v, float& lo, float& hi) {
    asm("mov.b64 {%0, %1}, %2;" : "=f"(lo), "=f"(hi) : "l"(v));
}
__device__ __forceinline__ u64 ffma2(u64 a, u64 b, u64 c) {
    u64 d;
    asm("fma.rn.f32x2 %0, %1, %2, %3;" : "=l"(d) : "l"(a), "l"(b), "l"(c));
    return d;
}
__device__ __forceinline__ float hsum(u64 v) {
    float lo, hi;
    unpack2(v, lo, hi);
    return lo + hi;
}

// ---- activations on the MUFU.TANH pipe: 1 MUFU each (was 2) ----
__device__ __forceinline__ float tanh_fast(float x) {
    float y;
    asm("tanh.approx.f32 %0, %1;" : "=f"(y) : "f"(x));
    return y;
}
__device__ __forceinline__ float sigmf(float x) {
    // sigmoid(x) = 0.5*tanh(0.5x) + 0.5
    return fmaf(0.5f, tanh_fast(0.5f * x), 0.5f);
}

// fp16x2 (k-pair of one gate) -> packed f32x2 u64
__device__ __forceinline__ u64 h2tof(unsigned int h2raw) {
    __half2 h = *reinterpret_cast<const __half2*>(&h2raw);
    float2 f = __half22float2(h);
    return pack2(f.x, f.y);
}

// h layout (one buffer = 1024 floats): h[ks:2][m:64][r:4][par:2], k = ks*128 + 2m + par
#define HADDRF(k, r) (((k) >> 7) * 512 + (((k) & 127) >> 1) * 8 + ((r) * 2) + ((k) & 1))

// one m-iter: 1 preloaded uint4 (4 gates x k-pair fp16) + 2 LDS.128 -> 16 ffma2
__device__ __forceinline__ void mv4x4(uint4 wr, const float* __restrict__ hb,
                                      int m, u64 (*__restrict__ acc)[4]) {
    u64 wi = h2tof(wr.x);
    u64 wf = h2tof(wr.y);
    u64 wg = h2tof(wr.z);
    u64 wo = h2tof(wr.w);
    const ulonglong2* hp = reinterpret_cast<const ulonglong2*>(hb + m * 8);
    ulonglong2 Ha = hp[0], Hb = hp[1];
    u64 H0 = Ha.x, H1 = Ha.y, H2 = Hb.x, H3 = Hb.y;
    acc[0][0] = ffma2(wi, H0, acc[0][0]);
    acc[0][1] = ffma2(wi, H1, acc[0][1]);
    acc[0][2] = ffma2(wi, H2, acc[0][2]);
    acc[0][3] = ffma2(wi, H3, acc[0][3]);
    acc[1][0] = ffma2(wf, H0, acc[1][0]);
    acc[1][1] = ffma2(wf, H1, acc[1][1]);
    acc[1][2] = ffma2(wf, H2, acc[1][2]);
    acc[1][3] = ffma2(wf, H3, acc[1][3]);
    acc[2][0] = ffma2(wg, H0, acc[2][0]);
    acc[2][1] = ffma2(wg, H1, acc[2][1]);
    acc[2][2] = ffma2(wg, H2, acc[2][2]);
    acc[2][3] = ffma2(wg, H3, acc[2][3]);
    acc[3][0] = ffma2(wo, H0, acc[3][0]);
    acc[3][1] = ffma2(wo, H1, acc[3][1]);
    acc[3][2] = ffma2(wo, H2, acc[3][2]);
    acc[3][3] = ffma2(wo, H3, acc[3][3]);
}

// one matvec pass (64 m-iters), depth-2 weight rotation (1 LDG.128/m)
__device__ __forceinline__ void mvpass(const __half2* __restrict__ wbase,
                                       const float* __restrict__ hb,
                                       u64 (*__restrict__ acc)[4]) {
    const uint4* wp = reinterpret_cast<const uint4*>(wbase);
    uint4 w0 = __ldg(wp);
    wp += 512;
#pragma unroll 4
    for (int m = 0; m < 64; m++) {
        uint4 w1 = __ldg(wp);   // overshoots into padding at m=63
        wp += 512;
        mv4x4(w0, hb, m, acc);
        w0 = w1;
    }
}

__global__ void __launch_bounds__(512) lstm_kernel(
    const float* __restrict__ x_in,   // (512,256,2)
    const float* __restrict__ W_ih1,  // (1024,2)
    const float* __restrict__ b_ih1, const float* __restrict__ b_hh1,
    const float* __restrict__ b_ih2, const float* __restrict__ b_hh2,
    const float* __restrict__ W_lin,  // (2,256)
    const float* __restrict__ b_lin,  // (2,)
    float* __restrict__ out)          // (512,256,2)
{
    // double-buffered h: [buf:2][1024 floats]
    __shared__ __align__(16) float sh1f[2 * 1024];
    __shared__ __align__(16) float sh2f[2 * 1024];
    __shared__ float sh_x[2][RR][2];
    __shared__ float sh_wl[2][256];

    const int tid  = threadIdx.x;
    const int ks   = tid & 1;        // k-half this thread accumulates
    const int j    = tid >> 1;       // hidden unit (0..255)
    const int b0   = blockIdx.x * RR;
    const int lane = tid & 31;
    const int warp = tid >> 5;
    const int rb   = ks * 2;         // my 2 batch rows: rb, rb+1

    // per-thread fp32 constants, all 4 gates of unit j (exact)
    float bias1[4], bias2[4], wx0[4], wx1[4];
#pragma unroll
    for (int q = 0; q < 4; q++) {
        int row = q * 256 + j;
        bias1[q] = b_ih1[row] + b_hh1[row];
        bias2[q] = b_ih2[row] + b_hh2[row];
        wx0[q] = W_ih1[row * 2 + 0];
        wx1[q] = W_ih1[row * 2 + 1];
    }
    if (tid < 256) {
        sh_wl[0][tid] = W_lin[tid];
        sh_wl[1][tid] = W_lin[256 + tid];
    }
    for (int i = tid; i < 2 * 1024; i += 512) { sh1f[i] = 0.0f; sh2f[i] = 0.0f; }
    if (tid < RR * 2) {  // stage x for t=0
        int r = tid >> 1, c = tid & 1;
        sh_x[0][r][c] = x_in[((b0 + r) * TT + 0) * 2 + c];
    }

    float c1[2] = {0.0f, 0.0f};
    float c2[2] = {0.0f, 0.0f};

    const float blin0 = b_lin[0], blin1 = b_lin[1];
    const int   woff  = (j * 2 + ks) * 4;   // half2 offset of my uint4
    const int   hw    = HADDRF(j, 0);       // h write base (+ r*2, + buf*1024)

    __syncthreads();

    for (int t = 0; t < TT; t++) {
        const int bw = t & 1;        // buffer written this step
        const int br = bw ^ 1;       // buffer holding prev-step h

        // stage x for t+1 (consumed at cell1 of t+1; S1+S2 barriers intervene)
        if (tid < RR * 2 && t + 1 < TT) {
            int r = tid >> 1, c = tid & 1;
            sh_x[(t + 1) & 1][r][c] = x_in[((b0 + r) * TT + t + 1) * 2 + c];
        }

        u64 acc[4][4];
#pragma unroll
        for (int q = 0; q < 4; q++)
#pragma unroll
            for (int r = 0; r < 4; r++) acc[q][r] = 0ULL;

        // ===== layer 1 matvec: h1_prev * Whh1^T (my k-half) =====
        mvpass(g_W1h + woff, sh1f + br * 1024 + ks * 512, acc);

        // reduce: k-parity hsum + cross-k-half shfl (partner = lane^1)
        float g[4][4];
#pragma unroll
        for (int q = 0; q < 4; q++)
#pragma unroll
            for (int r = 0; r < 4; r++) {
                float s = hsum(acc[q][r]);
                s += __shfl_xor_sync(0xffffffffu, s, 1);
                g[q][r] = s;
            }

        // cell 1 for my 2 rows -> write h1 into the OTHER buffer (no barrier:
        // sh1f[bw] was last read at step t-1's matvec1, sealed by t-1's barriers)
        {
            const float (*xb)[2] = sh_x[t & 1];
#pragma unroll
            for (int i = 0; i < 2; i++) {
                int r = rb + i;
                float x0 = xb[r][0], x1 = xb[r][1];
                float gi = g[0][r] + fmaf(x1, wx1[0], fmaf(x0, wx0[0], bias1[0]));
                float gf = g[1][r] + fmaf(x1, wx1[1], fmaf(x0, wx0[1], bias1[1]));
                float gg = g[2][r] + fmaf(x1, wx1[2], fmaf(x0, wx0[2], bias1[2]));
                float go = g[3][r] + fmaf(x1, wx1[3], fmaf(x0, wx0[3], bias1[3]));
                c1[i] = sigmf(gf) * c1[i] + sigmf(gi) * tanh_fast(gg);
                sh1f[bw * 1024 + hw + r * 2] = sigmf(go) * tanh_fast(c1[i]);
            }
        }
        __syncthreads();  // S1: h1_new visible; everyone past matvec1

#pragma unroll
        for (int q = 0; q < 4; q++)
#pragma unroll
            for (int r = 0; r < 4; r++) acc[q][r] = 0ULL;

        // ===== layer 2: h1_new * Wih2^T + h2_prev * Whh2^T =====
        mvpass(g_W2ah + woff, sh1f + bw * 1024 + ks * 512, acc);
        mvpass(g_W2bh + woff, sh2f + br * 1024 + ks * 512, acc);

#pragma unroll
        for (int q = 0; q < 4; q++)
#pragma unroll
            for (int r = 0; r < 4; r++) {
                float s = hsum(acc[q][r]);
                s += __shfl_xor_sync(0xffffffffu, s, 1);
                g[q][r] = s;
            }

        // cell 2 -> write h2 into the other buffer (sh2f[bw] last read at t-1)
#pragma unroll
        for (int i = 0; i < 2; i++) {
            int r = rb + i;
            float gi = g[0][r] + bias2[0];
            float gf = g[1][r] + bias2[1];
            float gg = g[2][r] + bias2[2];
            float go = g[3][r] + bias2[3];
            c2[i] = sigmf(gf) * c2[i] + sigmf(gi) * tanh_fast(gg);
            sh2f[bw * 1024 + hw + r * 2] = sigmf(go) * tanh_fast(c2[i]);
        }
        __syncthreads();  // S2: h2_new visible; everyone past matvec2

        // ===== y = h2 * W_lin^T + b_lin : warp r -> batch row r =====
        if (warp < RR) {
            int r = warp;
            const float* h2n = sh2f + bw * 1024;
            float v0 = 0.0f, v1 = 0.0f;
#pragma unroll
            for (int mm = 0; mm < 8; mm++) {
                int k = lane + mm * 32;
                float h = h2n[HADDRF(k, r)];
                v0 = fmaf(sh_wl[0][k], h, v0);
                v1 = fmaf(sh_wl[1][k], h, v1);
            }
#pragma unroll
            for (int off = 16; off; off >>= 1) {
                v0 += __shfl_xor_sync(0xffffffffu, v0, off);
                v1 += __shfl_xor_sync(0xffffffffu, v1, off);
            }
            if (lane == 0) {
                out[((b0 + r) * TT + t) * 2 + 0] = v0 + blin0;
                out[((b0 + r) * TT + t) * 2 + 1] = v1 + blin1;
            }
        }
        // S1 of step t+1 seals buffer rotation for laggards
    }
}

extern "C" void kernel_launch(void* const* d_in, const int* in_sizes, int n_in,
                              void* d_out, int out_size) {
    const float* inputs = (const float*)d_in[0];
    const float* W_ih1  = (const float*)d_in[1];
    const float* W_hh1  = (const float*)d_in[2];
    const float* b_ih1  = (const float*)d_in[3];
    const float* b_hh1  = (const float*)d_in[4];
    const float* W_ih2  = (const float*)d_in[5];
    const float* W_hh2  = (const float*)d_in[6];
    const float* b_ih2  = (const float*)d_in[7];
    const float* b_hh2  = (const float*)d_in[8];
    const float* W_lin  = (const float*)d_in[9];
    const float* b_lin  = (const float*)d_in[10];

    prep_kernel<<<512, 256>>>(W_hh1, W_ih2, W_hh2);
    lstm_kernel<<<NCTA, 512>>>(inputs, W_ih1, b_ih1, b_hh1, b_ih2, b_hh2,
                               W_lin, b_lin, (float*)d_out);
}